// round 17
// baseline (speedup 1.0000x reference)
#include <cuda_runtime.h>
#include <math.h>

#define N_NODES 50000
#define F_IN    128
#define H1      128
#define H2      64
#define E_TRAIN 600000
#define E_SCORE 200000
#define NB_SCAN 196                     // ceil(50000/256)

// Scratch buffers (device globals — no allocation allowed)
__device__ float g_dinv  [N_NODES];
__device__ int   g_cnt   [N_NODES];
__device__ int   g_rowptr[N_NODES + 1];
__device__ int   g_cursor[N_NODES];
__device__ int   g_bsum  [256];
__device__ int   g_esrc  [E_TRAIN];
__device__ float g_h0    [N_NODES * H1];
__device__ float g_h2p   [N_NODES * H2];
__device__ float g_agg2  [N_NODES * H2];

// ---------------------------------------------------------------- packed f32x2 helpers
__device__ __forceinline__ void fma2(unsigned long long& d,
                                     unsigned long long a,
                                     unsigned long long b) {
    asm("fma.rn.f32x2 %0, %1, %2, %0;" : "+l"(d) : "l"(a), "l"(b));
}
__device__ __forceinline__ float2 u2f(unsigned long long u) {
    float2 f;
    asm("mov.b64 {%0, %1}, %2;" : "=f"(f.x), "=f"(f.y) : "l"(u));
    return f;
}
__device__ __forceinline__ unsigned long long fdup(float a) {
    unsigned long long u;
    asm("mov.b64 %0, {%1, %1};" : "=l"(u) : "f"(a));
    return u;
}

// ---------------------------------------------------------------- degree/CSR build (R15-verbatim)
__global__ void k_zero_cnt() {
    int i = blockIdx.x * blockDim.x + threadIdx.x;
    if (i < N_NODES) g_cnt[i] = 0;
}

__global__ void k_count(const int* __restrict__ ei) {
    int e = blockIdx.x * blockDim.x + threadIdx.x;
    if (e < E_TRAIN) atomicAdd(&g_cnt[ei[E_TRAIN + e]], 1);   // col = target
}

__global__ void k_scan1() {
    __shared__ int wsum[8];
    int t = threadIdx.x;
    int i = blockIdx.x * 256 + t;
    int v = (i < N_NODES) ? g_cnt[i] : 0;
    int s = v;
#pragma unroll
    for (int o = 1; o < 32; o <<= 1) {
        int u = __shfl_up_sync(0xFFFFFFFFu, s, o);
        if ((t & 31) >= o) s += u;
    }
    if ((t & 31) == 31) wsum[t >> 5] = s;
    __syncthreads();
    if (t < 8) {
        int w = wsum[t];
        int e = w;
#pragma unroll
        for (int o = 1; o < 8; o <<= 1) {
            int u = __shfl_up_sync(0xFFu, e, o);
            if (t >= o) e += u;
        }
        wsum[t] = e - w;
    }
    __syncthreads();
    int incl = s + wsum[t >> 5];
    if (i < N_NODES) {
        g_rowptr[i] = incl - v;
        g_dinv[i]   = rsqrtf((float)(v + 1));
    }
    if (t == 255) g_bsum[blockIdx.x] = incl;
}

__global__ void k_scan3() {
    __shared__ int wsum[8];
    __shared__ int total;
    int t   = threadIdx.x;
    int bid = blockIdx.x;
    int v = (t < bid) ? g_bsum[t] : 0;
    int s = v;
#pragma unroll
    for (int o = 16; o; o >>= 1) s += __shfl_xor_sync(0xFFFFFFFFu, s, o);
    if ((t & 31) == 0) wsum[t >> 5] = s;
    __syncthreads();
    if (t == 0) {
        int acc = 0;
#pragma unroll
        for (int w = 0; w < 8; w++) acc += wsum[w];
        total = acc;
    }
    __syncthreads();
    int i = bid * 256 + t;
    if (i < N_NODES) {
        int r = g_rowptr[i] + total;
        g_rowptr[i] = r;
        g_cursor[i] = r;
    }
    if (i == 0) g_rowptr[N_NODES] = E_TRAIN;
}

__global__ void k_fill(const int* __restrict__ ei) {
    int e = blockIdx.x * blockDim.x + threadIdx.x;
    if (e >= E_TRAIN) return;
    int dst = ei[E_TRAIN + e];
    int p = atomicAdd(&g_cursor[dst], 1);
    g_esrc[p] = ei[e];
}

// ---------------------------------------------------------------- GEMM1 v2: g_h0 = x @ W1
// W1 fully resident in smem (staged once); x tiles double-buffered (prefetch
// chunk c+1 during compute of chunk c); ONE barrier per chunk. Inner loop = R9.
#define G1_WS_STRIDE 136                             // 128 + 8 pad
#define G1_XD_STRIDE 264                             // 2*128 + 8 pad
#define G1_SMEM (128 * G1_WS_STRIDE * 4 + 2 * 16 * G1_XD_STRIDE * 4)   // 103424
__global__ __launch_bounds__(256, 2) void k_gemm1(const float* __restrict__ x,
                                                  const float* __restrict__ W) {
    extern __shared__ float sm1[];
    float* Ws = sm1;                                 // [128][136]
    float* xd = sm1 + 128 * G1_WS_STRIDE;            // [2][16][264]
    const int tx   = threadIdx.x;
    const int tr   = tx >> 4;
    const int tc   = tx & 15;
    const int row0 = blockIdx.x * 128;

    // stage ALL of W: 4096 float4, 16/thread, coalesced
#pragma unroll
    for (int q = 0; q < 16; q++) {
        int idx = tx + 256 * q;
        int r = idx >> 5;
        int c = (idx & 31) * 4;
        *(float4*)&Ws[r * G1_WS_STRIDE + c] = *(const float4*)&W[r * H1 + c];
    }
    // stage x chunk 0 (duplicated layout)
#pragma unroll
    for (int q = 0; q < 2; q++) {
        int idx = tx + 256 * q;
        int row = idx >> 2;
        int kof = (idx & 3) * 4;
        float4 v = make_float4(0.f, 0.f, 0.f, 0.f);
        int grow = row0 + row;
        if (grow < N_NODES) v = *(const float4*)&x[grow * F_IN + kof];
        *(unsigned long long*)&xd[(kof + 0) * G1_XD_STRIDE + 2 * row] = fdup(v.x);
        *(unsigned long long*)&xd[(kof + 1) * G1_XD_STRIDE + 2 * row] = fdup(v.y);
        *(unsigned long long*)&xd[(kof + 2) * G1_XD_STRIDE + 2 * row] = fdup(v.z);
        *(unsigned long long*)&xd[(kof + 3) * G1_XD_STRIDE + 2 * row] = fdup(v.w);
    }
    __syncthreads();

    unsigned long long acc[8][4];
#pragma unroll
    for (int r = 0; r < 8; r++)
#pragma unroll
        for (int j = 0; j < 4; j++) acc[r][j] = 0ull;

    float4 pf[2];
    for (int c = 0; c < 8; c++) {
        // prefetch x chunk c+1 into registers (overlapped with compute below)
        if (c < 7) {
#pragma unroll
            for (int q = 0; q < 2; q++) {
                int idx = tx + 256 * q;
                int row = idx >> 2;
                int kof = (idx & 3) * 4;
                pf[q] = make_float4(0.f, 0.f, 0.f, 0.f);
                int grow = row0 + row;
                if (grow < N_NODES)
                    pf[q] = *(const float4*)&x[grow * F_IN + (c + 1) * 16 + kof];
            }
        }
        // compute chunk c from buffer c&1
        const float* xb = xd + (c & 1) * 16 * G1_XD_STRIDE;
#pragma unroll
        for (int kk = 0; kk < 16; kk++) {
            const ulonglong2* xp = (const ulonglong2*)&xb[kk * G1_XD_STRIDE + tr * 16];
            unsigned long long xa[8];
#pragma unroll
            for (int i = 0; i < 4; i++) {
                ulonglong2 p = xp[i];
                xa[2 * i + 0] = p.x;
                xa[2 * i + 1] = p.y;
            }
            const ulonglong2* wp =
                (const ulonglong2*)&Ws[(c * 16 + kk) * G1_WS_STRIDE + tc * 8];
            ulonglong2 w0 = wp[0], w1 = wp[1];
            unsigned long long wb[4] = { w0.x, w0.y, w1.x, w1.y };
#pragma unroll
            for (int r = 0; r < 8; r++)
#pragma unroll
                for (int j = 0; j < 4; j++)
                    fma2(acc[r][j], xa[r], wb[j]);
        }
        // store prefetch into the other buffer
        if (c < 7) {
            float* nb = xd + ((c + 1) & 1) * 16 * G1_XD_STRIDE;
#pragma unroll
            for (int q = 0; q < 2; q++) {
                int idx = tx + 256 * q;
                int row = idx >> 2;
                int kof = (idx & 3) * 4;
                *(unsigned long long*)&nb[(kof + 0) * G1_XD_STRIDE + 2 * row] = fdup(pf[q].x);
                *(unsigned long long*)&nb[(kof + 1) * G1_XD_STRIDE + 2 * row] = fdup(pf[q].y);
                *(unsigned long long*)&nb[(kof + 2) * G1_XD_STRIDE + 2 * row] = fdup(pf[q].z);
                *(unsigned long long*)&nb[(kof + 3) * G1_XD_STRIDE + 2 * row] = fdup(pf[q].w);
            }
        }
        __syncthreads();
    }

#pragma unroll
    for (int r = 0; r < 8; r++) {
        int grow = row0 + tr * 8 + r;
        if (grow < N_NODES) {
            float2 f0 = u2f(acc[r][0]), f1 = u2f(acc[r][1]);
            float2 f2 = u2f(acc[r][2]), f3 = u2f(acc[r][3]);
            float* o = &g_h0[grow * H1 + tc * 8];
            *(float4*)(o + 0) = make_float4(f0.x, f0.y, f1.x, f1.y);
            *(float4*)(o + 4) = make_float4(f2.x, f2.y, f3.x, f3.y);
        }
    }
}

// ---------------------------------------------------------------- FUSED agg1_gather + gemm2
// Block = 64 nodes. Phase 1: warp-per-node gather (bias + self-loop + ReLU) into smem.
// Phase 2: [64x128] @ W2[128x64] from smem -> g_h2p. No g_agg1 round-trip.
#define FX_STRIDE 132                                // 128 + 4 pad (bank shift)
#define FUSE_SMEM (64 * FX_STRIDE * 4 + 128 * 64 * 4)   // 33792 + 32768 = 66560
__global__ __launch_bounds__(256) void k_agg1_gemm2(const float* __restrict__ b1,
                                                    const float* __restrict__ W2) {
    extern __shared__ float sm2[];
    float* xs = sm2;                                 // [64][132] relu(agg1) rows
    float* Ws = sm2 + 64 * FX_STRIDE;                // [128][64]
    const int tx   = threadIdx.x;
    const int wid  = tx >> 5;
    const int lane = tx & 31;
    const int row0 = blockIdx.x * 64;

    // stage ALL of W2: 2048 float4, 8/thread
#pragma unroll
    for (int q = 0; q < 8; q++) {
        int idx = tx + 256 * q;
        ((float4*)Ws)[idx] = ((const float4*)W2)[idx];
    }

    // phase 1: gather 8 nodes per warp
    float4 bb = *(const float4*)&b1[lane * 4];
    for (int i = 0; i < 8; i++) {
        int lrow = wid * 8 + i;
        int node = row0 + lrow;
        if (node < N_NODES) {
            float di = g_dinv[node];
            float selfs = di * di;
            float4 acc = *(const float4*)&g_h0[node * H1 + lane * 4];
            acc.x = acc.x * selfs + bb.x;
            acc.y = acc.y * selfs + bb.y;
            acc.z = acc.z * selfs + bb.z;
            acc.w = acc.w * selfs + bb.w;
            int s = g_rowptr[node];
            int e = g_rowptr[node + 1];
            for (int k = s; k < e; k++) {
                int src = g_esrc[k];
                float nrm = di * g_dinv[src];
                float4 v = *(const float4*)&g_h0[src * H1 + lane * 4];
                acc.x += v.x * nrm;
                acc.y += v.y * nrm;
                acc.z += v.z * nrm;
                acc.w += v.w * nrm;
            }
            float* o = &xs[lrow * FX_STRIDE + lane * 4];
            o[0] = fmaxf(acc.x, 0.f);
            o[1] = fmaxf(acc.y, 0.f);
            o[2] = fmaxf(acc.z, 0.f);
            o[3] = fmaxf(acc.w, 0.f);
        }
    }
    __syncthreads();

    // phase 2: 64x64 GEMM from smem; thread tile 4 rows x 4 cols
    const int tr = tx >> 4;                          // rows tr*4..+3
    const int tc = tx & 15;                          // cols tc*4..+3
    float acc2[4][4];
#pragma unroll
    for (int r = 0; r < 4; r++)
#pragma unroll
        for (int j = 0; j < 4; j++) acc2[r][j] = 0.0f;

#pragma unroll 4
    for (int k0 = 0; k0 < H1; k0 += 4) {
        float4 xa[4];
#pragma unroll
        for (int r = 0; r < 4; r++)
            xa[r] = *(const float4*)&xs[(tr * 4 + r) * FX_STRIDE + k0];
        float4 w0 = *(const float4*)&Ws[(k0 + 0) * 64 + tc * 4];
        float4 w1 = *(const float4*)&Ws[(k0 + 1) * 64 + tc * 4];
        float4 w2 = *(const float4*)&Ws[(k0 + 2) * 64 + tc * 4];
        float4 w3 = *(const float4*)&Ws[(k0 + 3) * 64 + tc * 4];
#pragma unroll
        for (int r = 0; r < 4; r++) {
            acc2[r][0] += xa[r].x * w0.x + xa[r].y * w1.x + xa[r].z * w2.x + xa[r].w * w3.x;
            acc2[r][1] += xa[r].x * w0.y + xa[r].y * w1.y + xa[r].z * w2.y + xa[r].w * w3.y;
            acc2[r][2] += xa[r].x * w0.z + xa[r].y * w1.z + xa[r].z * w2.z + xa[r].w * w3.z;
            acc2[r][3] += xa[r].x * w0.w + xa[r].y * w1.w + xa[r].z * w2.w + xa[r].w * w3.w;
        }
    }

#pragma unroll
    for (int r = 0; r < 4; r++) {
        int grow = row0 + tr * 4 + r;
        if (grow < N_NODES)
            *(float4*)&g_h2p[grow * H2 + tc * 4] =
                make_float4(acc2[r][0], acc2[r][1], acc2[r][2], acc2[r][3]);
    }
}

// ---------------------------------------------------------------- agg2 gather: half-warp per node (R15-verbatim)
__global__ __launch_bounds__(256) void k_agg2_gather(const float* __restrict__ b2) {
    int node = (blockIdx.x * blockDim.x + threadIdx.x) >> 4;
    if (node >= N_NODES) return;
    int lane = threadIdx.x & 15;

    float di = g_dinv[node];
    float selfs = di * di;

    float4 acc = *(const float4*)&g_h2p[node * H2 + lane * 4];
    float4 bb  = *(const float4*)&b2[lane * 4];
    acc.x = acc.x * selfs + bb.x;
    acc.y = acc.y * selfs + bb.y;
    acc.z = acc.z * selfs + bb.z;
    acc.w = acc.w * selfs + bb.w;

    int s = g_rowptr[node];
    int e = g_rowptr[node + 1];
    for (int k = s; k < e; k++) {
        int src = g_esrc[k];
        float nrm = di * g_dinv[src];
        float4 v = *(const float4*)&g_h2p[src * H2 + lane * 4];
        acc.x += v.x * nrm;
        acc.y += v.y * nrm;
        acc.z += v.z * nrm;
        acc.w += v.w * nrm;
    }
    *(float4*)&g_agg2[node * H2 + lane * 4] = acc;
}

// ---------------------------------------------------------------- score: half-warp per edge (R15-verbatim)
__global__ __launch_bounds__(256) void k_score(const int* __restrict__ pos,
                                               const int* __restrict__ neg,
                                               float* __restrict__ out) {
    int w = (blockIdx.x * blockDim.x + threadIdx.x) >> 4;
    if (w >= 2 * E_SCORE) return;
    int lane = threadIdx.x & 15;
    int src, dst;
    if (w < E_SCORE) { src = pos[w];            dst = pos[E_SCORE + w]; }
    else             { int e = w - E_SCORE; src = neg[e]; dst = neg[E_SCORE + e]; }
    float4 a = *(const float4*)&g_agg2[src * H2 + lane * 4];
    float4 b = *(const float4*)&g_agg2[dst * H2 + lane * 4];
    float s = a.x * b.x + a.y * b.y + a.z * b.z + a.w * b.w;
#pragma unroll
    for (int o = 8; o; o >>= 1) s += __shfl_xor_sync(0xFFFFFFFFu, s, o);
    if (lane == 0) out[w] = s;
}

// ----------------------------------------------------------------
extern "C" void kernel_launch(void* const* d_in, const int* in_sizes, int n_in,
                              void* d_out, int out_size) {
    const float* x    = (const float*)d_in[0];
    const int*   tr   = (const int*)  d_in[1];   // [2, 600000]
    const int*   pos  = (const int*)  d_in[2];   // [2, 200000]
    const int*   neg  = (const int*)  d_in[3];   // [2, 200000]
    const float* W1   = (const float*)d_in[4];
    const float* b1   = (const float*)d_in[5];
    const float* W2   = (const float*)d_in[6];
    const float* b2   = (const float*)d_in[7];
    float* out = (float*)d_out;

    static cudaStream_t s2 = nullptr;
    static cudaEvent_t  ev_fork = nullptr, ev_join = nullptr;
    if (s2 == nullptr) {
        cudaStreamCreateWithFlags(&s2, cudaStreamNonBlocking);
        cudaEventCreateWithFlags(&ev_fork, cudaEventDisableTiming);
        cudaEventCreateWithFlags(&ev_join, cudaEventDisableTiming);
        cudaFuncSetAttribute(k_gemm1, cudaFuncAttributeMaxDynamicSharedMemorySize, G1_SMEM);
        cudaFuncSetAttribute(k_agg1_gemm2, cudaFuncAttributeMaxDynamicSharedMemorySize, FUSE_SMEM);
    }

    // fork s2 off the main (capture) stream
    cudaEventRecord(ev_fork, 0);
    cudaStreamWaitEvent(s2, ev_fork, 0);

    // CSR build on side stream (independent of gemm1)
    k_zero_cnt<<<(N_NODES + 255) / 256, 256, 0, s2>>>();
    k_count   <<<(E_TRAIN + 255) / 256, 256, 0, s2>>>(tr);
    k_scan1   <<<NB_SCAN, 256, 0, s2>>>();
    k_scan3   <<<NB_SCAN, 256, 0, s2>>>();
    k_fill    <<<(E_TRAIN + 255) / 256, 256, 0, s2>>>(tr);
    cudaEventRecord(ev_join, s2);

    // GEMM1 on main stream, concurrent with CSR build
    k_gemm1<<<(N_NODES + 127) / 128, 256, G1_SMEM>>>(x, W1);

    // join: fused layer needs gemm1 (main) + CSR (s2)
    cudaStreamWaitEvent(0, ev_join, 0);

    // Fused agg1 + gemm2
    k_agg1_gemm2<<<(N_NODES + 63) / 64, 256, FUSE_SMEM>>>(b1, W2);

    // Layer 2 aggregation + scores
    k_agg2_gather<<<(N_NODES * 16 + 255) / 256, 256>>>(b2);
    k_score<<<(2 * E_SCORE * 16 + 255) / 256, 256>>>(pos, neg, out);
}